// round 6
// baseline (speedup 1.0000x reference)
#include <cuda_runtime.h>
#include <cuda_bf16.h>

#define BB 4
#define TT 512
#define VV 8000
#define HH 7
#define VP 8192   // padded vocab stride

// Scratch (allocation-free rule: __device__ globals)
__device__ float g_vocab[3][HH][VP];   // [0]=angle 2*pi*f*h, [1]=A/h^d * sin, [2]=A/h^d * cos
__device__ float g_C[BB * TT * VV];    // 65.5 MB

// ---------------------------------------------------------------------------
// Kernel A: build per-vocab harmonic tables (token rows are gathers of these)
// ---------------------------------------------------------------------------
__global__ void build_tables(const float* __restrict__ freq,
                             const float* __restrict__ amp,
                             const float* __restrict__ decay) {
    int v = blockIdx.x * blockDim.x + threadIdx.x;
    if (v >= VV) return;
    float f   = freq[v];
    float A   = amp[v];
    float dec = decay[0];
    const float TWO_PI = 6.2831853071795864769f;
#pragma unroll
    for (int j = 0; j < HH; j++) {
        float h   = (float)(j + 1);
        float ang = TWO_PI * f * h;
        float Ah  = A / powf(h, dec);
        float s, c;
        sincosf(ang, &s, &c);
        g_vocab[0][j][v] = ang;
        g_vocab[1][j][v] = Ah * s;
        g_vocab[2][j][v] = Ah * c;
    }
}

// ---------------------------------------------------------------------------
// Kernel B (factored form):
//   C[b,t,v] = 2 * sum_i [ sa_i * S1_i + ca_i * S2_i ]
//   S1_i = sum_j P_ij * g_ij,  S2_i = sum_j Q_ij * g_ij
//   normal: (P,Q,g) = (vcs_j, -vs_j, 1/(a_i - b_j))  -> AA*sin(r)/r
//   near  : (P,Q,g) = (vs_j,   vcs_j, 1)             -> AA*cos(r) ~ limit
// 3 fma-pipe ops/term + 3 FSEL (alu) + 1 FSETP + 1 MUFU.RCP
// ---------------------------------------------------------------------------
__global__ void __launch_bounds__(256) wave_C(const int* __restrict__ ids) {
    __shared__ float sA[16][8];
    __shared__ float sS[16][8];
    __shared__ float sC[16][8];
    __shared__ int   sid[16];

    const int b   = blockIdx.z;
    const int t0  = blockIdx.y * 16;
    const int tid = threadIdx.x;

    if (tid < 16) sid[tid] = ids[b * TT + t0 + tid];
    __syncthreads();
    if (tid < 16 * HH) {                 // 112 (tt,i) pairs
        int ttl = tid / HH, i = tid % HH;
        int u   = sid[ttl];
        sA[ttl][i] = g_vocab[0][i][u];
        sS[ttl][i] = g_vocab[1][i][u];
        sC[ttl][i] = g_vocab[2][i][u];
    }
    __syncthreads();

    const int v  = blockIdx.x * 256 + tid;
    const int vc = (v < VV) ? v : (VV - 1);
    const bool ok = (v < VV);

    float vb[HH], vs[HH], vcs[HH], nvs[HH];
#pragma unroll
    for (int j = 0; j < HH; j++) {
        vb[j]  = g_vocab[0][j][vc];
        vs[j]  = g_vocab[1][j][vc];
        vcs[j] = g_vocab[2][j][vc];
        nvs[j] = -vs[j];
    }

#pragma unroll 1                         // keep body in I$
    for (int ttl = 0; ttl < 16; ttl++) {
        float acc = 0.0f;
#pragma unroll
        for (int i = 0; i < HH; i++) {
            const float a  = sA[ttl][i];
            const float sa = sS[ttl][i];
            const float ca = sC[ttl][i];
            float S1 = 0.0f, S2 = 0.0f;
#pragma unroll
            for (int j = 0; j < HH; j++) {
                float r = a - vb[j];
                float d;
                asm("rcp.approx.f32 %0, %1;" : "=f"(d) : "f"(r));
                bool  m = fabsf(r) < 1e-2f;
                float P = m ? vs[j]  : vcs[j];
                float Q = m ? vcs[j] : nvs[j];
                float g = m ? 1.0f   : d;
                S1 = fmaf(P, g, S1);
                S2 = fmaf(Q, g, S2);
            }
            acc = fmaf(sa, S1, acc);
            acc = fmaf(ca, S2, acc);
        }
        if (ok) g_C[(size_t)((b * TT + t0 + ttl)) * VV + v] = 2.0f * acc;
    }
}

// ---------------------------------------------------------------------------
// Kernel C: exclusive cumsum over t per (b,v) column; 8-wide load batching
// ---------------------------------------------------------------------------
__global__ void __launch_bounds__(256) cumshift(float* __restrict__ out) {
    int idx = blockIdx.x * blockDim.x + threadIdx.x;
    if (idx >= BB * VV) return;
    int b = idx / VV;
    int v = idx - b * VV;
    const float* crow = g_C + (size_t)b * TT * VV + v;
    float*       orow = out + (size_t)b * TT * VV + v;
    float run = 0.0f;
#pragma unroll 1
    for (int t = 0; t < TT; t += 8) {
        float x[8];
#pragma unroll
        for (int k = 0; k < 8; k++) x[k] = crow[(size_t)(t + k) * VV];
#pragma unroll
        for (int k = 0; k < 8; k++) { orow[(size_t)(t + k) * VV] = run; run += x[k]; }
    }
}

// ---------------------------------------------------------------------------
extern "C" void kernel_launch(void* const* d_in, const int* in_sizes, int n_in,
                              void* d_out, int out_size) {
    const int*   ids   = (const int*)d_in[0];
    const float* freq  = (const float*)d_in[1];
    const float* amp   = (const float*)d_in[2];
    const float* decay = (const float*)d_in[3];
    // d_in[4] = chunk_size: result independent of chunking; ignored.

    build_tables<<<(VV + 255) / 256, 256>>>(freq, amp, decay);

    dim3 gridB((VV + 255) / 256, TT / 16, BB);
    wave_C<<<gridB, 256>>>(ids);

    cumshift<<<(BB * VV + 255) / 256, 256>>>((float*)d_out);
}

// round 10
// speedup vs baseline: 1.2749x; 1.2749x over previous
#include <cuda_runtime.h>
#include <cuda_bf16.h>

#define BB 4
#define TT 512
#define VV 8000
#define HH 7
#define VP 8192   // padded vocab stride
#define GUARD_TH 4e-3f

// Scratch (allocation-free rule: __device__ globals)
__device__ float g_vocab[3][HH][VP];   // [0]=angle 2*pi*f*h, [1]=A/h^d*sin, [2]=A/h^d*cos
__device__ float g_C[BB * TT * VV];    // 65.5 MB
__device__ int   g_pad_sink;

// ---------------------------------------------------------------------------
// Kernel A: per-vocab harmonic tables (token rows are gathers of these)
// ---------------------------------------------------------------------------
__global__ void build_tables(const float* __restrict__ freq,
                             const float* __restrict__ amp,
                             const float* __restrict__ decay) {
    int v = blockIdx.x * blockDim.x + threadIdx.x;
    if (v >= VV) return;
    float f   = freq[v];
    float A   = amp[v];
    float dec = decay[0];
    const float TWO_PI = 6.2831853071795864769f;
#pragma unroll
    for (int j = 0; j < HH; j++) {
        float h   = (float)(j + 1);
        float ang = TWO_PI * f * h;
        float Ah  = A / powf(h, dec);
        float s, c;
        sincosf(ang, &s, &c);
        g_vocab[0][j][v] = ang;
        g_vocab[1][j][v] = Ah * s;
        g_vocab[2][j][v] = Ah * c;
    }
}

// ---------------------------------------------------------------------------
// Kernel B: unguarded fast body (FADD + RCP + 2 FMA + FMNMX per term),
// rare guarded recompute per (thread,ttl) when any |r| < GUARD_TH.
// ---------------------------------------------------------------------------
__global__ void __launch_bounds__(256) wave_C(const int* __restrict__ ids) {
    __shared__ float sA[16][8];
    __shared__ float sS[16][8];
    __shared__ float sC[16][8];
    __shared__ int   sid[16];

    const int b   = blockIdx.z;
    const int t0  = blockIdx.y * 16;
    const int tid = threadIdx.x;

    if (tid < 16) sid[tid] = ids[b * TT + t0 + tid];
    __syncthreads();
    if (tid < 16 * HH) {                 // 112 (tt,i) pairs
        int ttl = tid / HH, i = tid % HH;
        int u   = sid[ttl];
        sA[ttl][i] = g_vocab[0][i][u];
        sS[ttl][i] = g_vocab[1][i][u];
        sC[ttl][i] = g_vocab[2][i][u];
    }
    __syncthreads();

    const int v  = blockIdx.x * 256 + tid;
    const int vc = (v < VV) ? v : (VV - 1);
    const bool ok = (v < VV);

    float vb[HH], vs[HH], vcs[HH], nvs[HH];
#pragma unroll
    for (int j = 0; j < HH; j++) {
        vb[j]  = g_vocab[0][j][vc];
        vs[j]  = g_vocab[1][j][vc];
        vcs[j] = g_vocab[2][j][vc];
        nvs[j] = -vs[j];
    }

#pragma unroll 1                         // keep the two bodies in I$ once
    for (int ttl = 0; ttl < 16; ttl++) {
        float accT = 0.0f;
        float rmin = 1e30f;
#pragma unroll
        for (int i = 0; i < HH; i++) {
            const float a  = sA[ttl][i];
            const float sa = sS[ttl][i];
            const float ca = sC[ttl][i];
            float S1 = 0.0f, S2 = 0.0f;
#pragma unroll
            for (int j = 0; j < HH; j++) {
                float r = a - vb[j];
                float d;
                asm("rcp.approx.f32 %0, %1;" : "=f"(d) : "f"(r));
                rmin = fminf(rmin, fabsf(r));
                S1 = fmaf(vcs[j], d, S1);
                S2 = fmaf(nvs[j], d, S2);
            }
            accT = fmaf(sa, S1, accT);
            accT = fmaf(ca, S2, accT);
        }
        if (rmin < GUARD_TH) {
            // Rare guarded recompute (R1-validated math; same threshold).
            accT = 0.0f;
#pragma unroll
            for (int i = 0; i < HH; i++) {
                const float a  = sA[ttl][i];
                const float sa = sS[ttl][i];
                const float ca = sC[ttl][i];
#pragma unroll
                for (int j = 0; j < HH; j++) {
                    float r = a - vb[j];
                    float d;
                    asm("rcp.approx.f32 %0, %1;" : "=f"(d) : "f"(r));
                    float num = fmaf(sa, vcs[j], ca * nvs[j]);   // AA*sin(r)
                    float val = num * d;
                    float alt = fmaf(sa, vs[j], ca * vcs[j]);    // AA*cos(r) ~ limit
                    accT += (fabsf(r) < GUARD_TH) ? alt : val;
                }
            }
        }
        if (ok) g_C[(size_t)((b * TT + t0 + ttl)) * VV + v] = 2.0f * accT;
    }
}

// ---------------------------------------------------------------------------
// Kernel C: exclusive cumsum over t per (b,v) column; 8-wide load batching
// ---------------------------------------------------------------------------
__global__ void __launch_bounds__(256) cumshift(float* __restrict__ out) {
    int idx = blockIdx.x * blockDim.x + threadIdx.x;
    if (idx >= BB * VV) return;
    int b = idx / VV;
    int v = idx - b * VV;
    const float* crow = g_C + (size_t)b * TT * VV + v;
    float*       orow = out + (size_t)b * TT * VV + v;
    float run = 0.0f;
#pragma unroll 1
    for (int t = 0; t < TT; t += 8) {
        float x[8];
#pragma unroll
        for (int k = 0; k < 8; k++) x[k] = crow[(size_t)(t + k) * VV];
#pragma unroll
        for (int k = 0; k < 8; k++) { orow[(size_t)(t + k) * VV] = run; run += x[k]; }
    }
}

// Pad kernel: makes the launch cycle length 4 so ncu (-s 5 -c 1) lands on
// wave_C instead of build_tables. Deterministic, ~1us.
__global__ void pad_k() { if (threadIdx.x == 0) g_pad_sink = 1; }

// ---------------------------------------------------------------------------
extern "C" void kernel_launch(void* const* d_in, const int* in_sizes, int n_in,
                              void* d_out, int out_size) {
    const int*   ids   = (const int*)d_in[0];
    const float* freq  = (const float*)d_in[1];
    const float* amp   = (const float*)d_in[2];
    const float* decay = (const float*)d_in[3];
    // d_in[4] = chunk_size: result independent of chunking; ignored.

    build_tables<<<(VV + 255) / 256, 256>>>(freq, amp, decay);

    dim3 gridB((VV + 255) / 256, TT / 16, BB);
    wave_C<<<gridB, 256>>>(ids);

    cumshift<<<(BB * VV + 255) / 256, 256>>>((float*)d_out);

    pad_k<<<1, 32>>>();
}